// round 14
// baseline (speedup 1.0000x reference)
#include <cuda_runtime.h>
#include <cuda_bf16.h>
#include <cstdint>

#define TT   1024
#define BB   2
#define HH   128
#define NIN  1024
#define MM   (BB * TT)          // 2048
#define NN   (2 * HH)           // 256
#define CH_T 128
#define NCH  (TT / CH_T)        // 8

#define U_ELEMS   (BB * TT * NIN)
#define LAM_ELEMS (HH)
#define B_ELEMS   (HH * NIN)

// GEMM tiling: CTA 64m x 64n, physical-k chunks of 128. B tiles via cp.async;
// u fp32 prefetched to registers and split to bf16 hi/lo in-kernel.
#define MT 64
#define NT 64
#define KT2 128
#define NPC (NIN / KT2)         // 8
#define TILE_B (64 * 256)       // 16384 bytes per operand tile
#define BUF_B  (4 * TILE_B)     // 65536 per buffer (uhi,ulo,Bhi,Blo)
#define GEMM_SMEM (2 * BUF_B)   // 131072

// device scratch (B-side split only; u split happens inside gemm)
__device__ __nv_bfloat16 g_Bhi[NN * NIN];
__device__ __nv_bfloat16 g_Blo[NN * NIN];
__device__ float2 g_bu[MM * HH];                // bu[(b*HH+h)*TT + t]
__device__ float2 g_part[BB * HH][NCH - 1][HH]; // per-chunk partial states

// ---- PTX helpers ----------------------------------------------------------
__device__ __forceinline__ uint32_t smem_u32(const void* p) {
    uint32_t a;
    asm("{ .reg .u64 t; cvta.to.shared.u64 t, %1; cvt.u32.u64 %0, t; }"
        : "=r"(a) : "l"(p));
    return a;
}
__device__ __forceinline__ uint32_t sw128(uint32_t off) {
    return off ^ ((off >> 3) & 0x70);
}
__device__ __forceinline__ void cp16(uint32_t dst, const void* src) {
    asm volatile("cp.async.cg.shared.global [%0], [%1], 16;"
                 :: "r"(dst), "l"(src));
}
__device__ __forceinline__ void cp_commit() {
    asm volatile("cp.async.commit_group;");
}
template <int N> __device__ __forceinline__ void cp_wait() {
    asm volatile("cp.async.wait_group %0;" :: "n"(N));
}
__device__ __forceinline__ void sts128(uint32_t dst, uint32_t a, uint32_t b,
                                       uint32_t c, uint32_t d) {
    asm volatile("st.shared.v4.b32 [%0], {%1,%2,%3,%4};"
                 :: "r"(dst), "r"(a), "r"(b), "r"(c), "r"(d) : "memory");
}
__device__ __forceinline__ void ldsm4(uint32_t& r0, uint32_t& r1,
                                      uint32_t& r2, uint32_t& r3,
                                      uint32_t addr) {
    asm volatile("ldmatrix.sync.aligned.m8n8.x4.shared.b16 {%0,%1,%2,%3}, [%4];"
                 : "=r"(r0), "=r"(r1), "=r"(r2), "=r"(r3) : "r"(addr));
}
__device__ __forceinline__ void mma_bf16(float& c0, float& c1, float& c2,
                                         float& c3, uint32_t a0, uint32_t a1,
                                         uint32_t a2, uint32_t a3,
                                         uint32_t b0, uint32_t b1) {
    asm volatile(
        "mma.sync.aligned.m16n8k16.row.col.f32.bf16.bf16.f32 "
        "{%0,%1,%2,%3}, {%4,%5,%6,%7}, {%8,%9}, {%0,%1,%2,%3};"
        : "+f"(c0), "+f"(c1), "+f"(c2), "+f"(c3)
        : "r"(a0), "r"(a1), "r"(a2), "r"(a3), "r"(b0), "r"(b1));
}
__device__ __forceinline__ void stg_cs_v4(float* p, float a, float b,
                                          float c, float d) {
    asm volatile("st.global.cs.v4.f32 [%0], {%1,%2,%3,%4};"
                 :: "l"(p), "f"(a), "f"(b), "f"(c), "f"(d) : "memory");
}
__device__ __forceinline__ float2 zoh_L(float ar, float ai, float d) {
    float er = expf(ar * d);
    return make_float2(er * cosf(ai * d), er * sinf(ai * d));
}
__device__ __forceinline__ uint32_t pack_bf16(float a, float b) {
    unsigned short ha = __bfloat16_as_ushort(__float2bfloat16(a));
    unsigned short hb = __bfloat16_as_ushort(__float2bfloat16(b));
    return (uint32_t)ha | ((uint32_t)hb << 16);
}

// ---------------------------------------------------------------------------
// prep (B-only, high-MLP): 64 blocks x 256 threads, 16 k per thread.
// Bw = w*(bre + i*bim); bf16 hi/lo, layout [n][k], n = 2h + comp.
// ---------------------------------------------------------------------------
__global__ void prep_kernel(const float* __restrict__ bre,
                            const float* __restrict__ bim,
                            const float* __restrict__ lre,
                            const float* __restrict__ lim,
                            const float* __restrict__ delta) {
    if (!bre || !bim || !lre || !lim) return;
    float d = delta ? delta[0] : 0.01f;
    int idx = blockIdx.x * 256 + threadIdx.x;   // 0..16383
    int n = idx >> 6, k0 = (idx & 63) * 16;
    int h = n >> 1;
    const float4* brp = reinterpret_cast<const float4*>(bre + (size_t)h * NIN + k0);
    const float4* bip = reinterpret_cast<const float4*>(bim + (size_t)h * NIN + k0);
    float4 vr[4], vi[4];
    #pragma unroll
    for (int i = 0; i < 4; i++) { vr[i] = brp[i]; vi[i] = bip[i]; }
    float ar = lre[h], ai = lim[h];
    float2 L = zoh_L(ar, ai, d);
    float nr = L.x - 1.0f, ni = L.y;
    float inv = 1.0f / (ar * ar + ai * ai);
    float wr = (nr * ar + ni * ai) * inv;
    float wi = (ni * ar - nr * ai) * inv;
    const float* br = reinterpret_cast<const float*>(vr);
    const float* bi = reinterpret_cast<const float*>(vi);
    bool im = (n & 1);
    uint32_t vh[8], vl[8];
    #pragma unroll
    for (int i = 0; i < 8; i++) {
        float a = im ? (wr * bi[2*i]   + wi * br[2*i])
                     : (wr * br[2*i]   - wi * bi[2*i]);
        float b = im ? (wr * bi[2*i+1] + wi * br[2*i+1])
                     : (wr * br[2*i+1] - wi * bi[2*i+1]);
        float ah = __bfloat162float(__float2bfloat16(a));
        float bh = __bfloat162float(__float2bfloat16(b));
        vh[i] = pack_bf16(ah, bh);
        vl[i] = pack_bf16(a - ah, b - bh);
    }
    int e0 = n * NIN + k0;
    uint4* dh = reinterpret_cast<uint4*>(g_Bhi + e0);
    uint4* dl = reinterpret_cast<uint4*>(g_Blo + e0);
    dh[0] = make_uint4(vh[0], vh[1], vh[2], vh[3]);
    dh[1] = make_uint4(vh[4], vh[5], vh[6], vh[7]);
    dl[0] = make_uint4(vl[0], vl[1], vl[2], vl[3]);
    dl[1] = make_uint4(vl[4], vl[5], vl[6], vl[7]);
}

// ---------------------------------------------------------------------------
// GEMM with fused u split: B tiles via cp.async (double-buffered); u fp32
// prefetched into registers during the previous chunk's MMA, converted to
// swizzled bf16 hi/lo smem tiles at the top of each chunk.
// One __syncthreads per chunk (ordering proof in commit message).
// Grid (32, 4) = 128 CTAs, 256 threads.
// ---------------------------------------------------------------------------
__global__ void __launch_bounds__(256, 1)
gemm_kernel(const float* __restrict__ u) {
    if (!u) return;
    extern __shared__ __align__(1024) uint8_t smem[];

    int tid = threadIdx.x, wid = tid >> 5, lane = tid & 31;
    int m0 = blockIdx.x * MT;
    int n0 = blockIdx.y * NT;
    int warp_m = wid & 1;
    int warp_n = wid >> 1;

    uint32_t sbase = smem_u32(smem);
    auto tile_base = [&](int buf, int t) -> uint32_t {
        return sbase + (uint32_t)buf * BUF_B + (uint32_t)t * TILE_B;
    };

    // u conversion mapping: thread -> (row r, quarter q); covers k [32q,32q+32)
    int cr = tid >> 2;          // 0..63
    int cq = tid & 3;           // 0..3
    uint32_t csub   = (uint32_t)(cq >> 1) * 8192;
    uint32_t cinner = (uint32_t)(cq & 1) * 64;
    uint32_t csts[4];
    #pragma unroll
    for (int j2 = 0; j2 < 4; j2++)
        csts[j2] = csub + sw128((uint32_t)(cr * 128) + cinner + 16 * j2);

    uint32_t offA[2][8], offB[8];
    {
        uint32_t rowA = (uint32_t)(warp_m * 32 + (lane & 15));
        uint32_t kbA  = (uint32_t)((lane >> 4) * 16);
        uint32_t rowB = (uint32_t)(warp_n * 16 + (lane & 7) + ((lane >> 4) << 3));
        uint32_t kbB  = (uint32_t)(((lane >> 3) & 1) * 16);
        #pragma unroll
        for (int s = 0; s < 8; s++) {
            uint32_t sub = (uint32_t)(s >> 2) * 8192;
            #pragma unroll
            for (int mt = 0; mt < 2; mt++)
                offA[mt][s] = sub + sw128((rowA + mt * 16) * 128
                                          + (s & 3) * 32 + kbA);
            offB[s] = sub + sw128(rowB * 128 + (s & 3) * 32 + kbB);
        }
    }

    auto load_Btile = [&](uint32_t dstbase, const __nv_bfloat16* g) {
        #pragma unroll
        for (int i = 0; i < 4; i++) {
            int idx = i * 256 + tid;
            int r = idx >> 4, s = idx & 15;
            cp16(dstbase + (uint32_t)((s >> 3) * 8192)
                         + sw128((uint32_t)(r * 128 + (s & 7) * 16)),
                 g + (size_t)r * NIN + s * 8);
        }
    };
    auto load_B = [&](int c, int buf) {
        int k0 = c * KT2;
        load_Btile(tile_base(buf, 2), g_Bhi + (size_t)n0 * NIN + k0);
        load_Btile(tile_base(buf, 3), g_Blo + (size_t)n0 * NIN + k0);
        cp_commit();
    };

    float4 uf[8];
    auto prefetch_u = [&](int c) {
        const float* gu = u + (size_t)(m0 + cr) * NIN + c * KT2 + cq * 32;
        #pragma unroll
        for (int i = 0; i < 8; i++)
            uf[i] = *reinterpret_cast<const float4*>(gu + 4 * i);
    };

    auto convert_u = [&](int buf) {
        uint32_t hb = tile_base(buf, 0);
        uint32_t lb = tile_base(buf, 1);
        uint32_t vh[16], vl[16];
        #pragma unroll
        for (int i = 0; i < 8; i++) {
            float f0 = uf[i].x, f1 = uf[i].y, f2 = uf[i].z, f3 = uf[i].w;
            float h0 = __bfloat162float(__float2bfloat16(f0));
            float h1 = __bfloat162float(__float2bfloat16(f1));
            float h2 = __bfloat162float(__float2bfloat16(f2));
            float h3 = __bfloat162float(__float2bfloat16(f3));
            vh[2*i]   = pack_bf16(h0, h1);
            vh[2*i+1] = pack_bf16(h2, h3);
            vl[2*i]   = pack_bf16(f0 - h0, f1 - h1);
            vl[2*i+1] = pack_bf16(f2 - h2, f3 - h3);
        }
        #pragma unroll
        for (int j2 = 0; j2 < 4; j2++) {
            sts128(hb + csts[j2], vh[4*j2], vh[4*j2+1], vh[4*j2+2], vh[4*j2+3]);
            sts128(lb + csts[j2], vl[4*j2], vl[4*j2+1], vl[4*j2+2], vl[4*j2+3]);
        }
    };

    float acc[2][2][4];
    #pragma unroll
    for (int i = 0; i < 2; i++)
        #pragma unroll
        for (int j = 0; j < 2; j++)
            #pragma unroll
            for (int q = 0; q < 4; q++) acc[i][j][q] = 0.f;

    prefetch_u(0);
    load_B(0, 0);

    for (int c = 0; c < NPC; c++) {
        int buf = c & 1;
        convert_u(buf);            // chunk c u regs -> smem (buf)
        cp_wait<0>();              // B tiles for chunk c arrived
        __syncthreads();           // all data visible; all warps done MMA c-1
        if (c + 1 < NPC) {
            load_B(c + 1, buf ^ 1);  // safe: MMA c-1 (buf^1) done per sync
            prefetch_u(c + 1);       // LDG latency hidden under MMA below
        }

        #pragma unroll
        for (int term = 0; term < 3; term++) {
            uint32_t Ab = tile_base(buf, term == 2 ? 1 : 0);
            uint32_t Bb = tile_base(buf, term == 1 ? 3 : 2);
            #pragma unroll
            for (int s = 0; s < 8; s++) {
                uint32_t a0[4], a1[4], b[4];
                ldsm4(a0[0], a0[1], a0[2], a0[3], Ab + offA[0][s]);
                ldsm4(a1[0], a1[1], a1[2], a1[3], Ab + offA[1][s]);
                ldsm4(b[0],  b[1],  b[2],  b[3],  Bb + offB[s]);
                mma_bf16(acc[0][0][0], acc[0][0][1], acc[0][0][2], acc[0][0][3],
                         a0[0], a0[1], a0[2], a0[3], b[0], b[1]);
                mma_bf16(acc[0][1][0], acc[0][1][1], acc[0][1][2], acc[0][1][3],
                         a0[0], a0[1], a0[2], a0[3], b[2], b[3]);
                mma_bf16(acc[1][0][0], acc[1][0][1], acc[1][0][2], acc[1][0][3],
                         a1[0], a1[1], a1[2], a1[3], b[0], b[1]);
                mma_bf16(acc[1][1][0], acc[1][1][1], acc[1][1][2], acc[1][1][3],
                         a1[0], a1[1], a1[2], a1[3], b[2], b[3]);
            }
        }
    }

    int hb = (n0 >> 1) + warp_n * 8;
    #pragma unroll
    for (int mt = 0; mt < 2; mt++) {
        #pragma unroll
        for (int nt = 0; nt < 2; nt++) {
            int h = hb + nt * 4 + (lane & 3);
            int m1 = m0 + warp_m * 32 + mt * 16 + (lane >> 2);
            int b1 = m1 >> 10, t1 = m1 & 1023;
            g_bu[((size_t)b1 * HH + h) * TT + t1] =
                make_float2(acc[mt][nt][0], acc[mt][nt][1]);
            int m2 = m1 + 8;
            int b2 = m2 >> 10, t2 = m2 & 1023;
            g_bu[((size_t)b2 * HH + h) * TT + t2] =
                make_float2(acc[mt][nt][2], acc[mt][nt][3]);
        }
    }
}

// ---------------------------------------------------------------------------
// Partial kernel: A_c = local scan of chunk c from zero. Grid (256, 7), 128.
// ---------------------------------------------------------------------------
__global__ void partial_kernel(const float* __restrict__ lre,
                               const float* __restrict__ lim,
                               const float* __restrict__ delta) {
    __shared__ float2 sbu[CH_T];
    int bh = blockIdx.x;
    int ch = blockIdx.y;
    int h2 = threadIdx.x;

    sbu[h2] = g_bu[(size_t)bh * TT + ch * CH_T + h2];
    __syncthreads();

    float d  = delta ? delta[0] : 0.01f;
    float2 L = zoh_L(lre[h2], lim[h2], d);

    float xr = 0.f, xi = 0.f;
    #pragma unroll 4
    for (int t = 0; t < CH_T; t++) {
        float2 c = sbu[t];
        float nr = fmaf(L.x, xr, fmaf(-L.y, xi, c.x));
        float ni = fmaf(L.x, xi, fmaf( L.y, xr, c.y));
        xr = nr; xi = ni;
    }
    g_part[bh][ch][h2] = make_float2(xr, xi);
}

// ---------------------------------------------------------------------------
// FAST chunk kernel (proven): lane owns 4 h2; warp owns a bh row.
// Grid (64, 8), 128 threads. Streaming float4 stores.
// ---------------------------------------------------------------------------
__global__ void __launch_bounds__(128)
chunk_fast_kernel(float* __restrict__ out,
                  const float* __restrict__ lre,
                  const float* __restrict__ lim,
                  const float* __restrict__ delta) {
    __shared__ float2 sbu[4][CH_T];

    int tid = threadIdx.x;
    int w = tid >> 5, j = tid & 31;
    int bh    = blockIdx.x * 4 + w;
    int chunk = blockIdx.y;
    int t0    = chunk * CH_T;

    const float2* src = g_bu + (size_t)bh * TT + t0;
    #pragma unroll
    for (int i = 0; i < 4; i++) sbu[w][i * 32 + j] = src[i * 32 + j];
    __syncwarp();

    float d = delta ? delta[0] : 0.01f;
    float Lx[4], Ly[4], xr[4], xi[4];
    #pragma unroll
    for (int q = 0; q < 4; q++) {
        int h2 = 4 * j + q;
        float2 L = zoh_L(lre[h2], lim[h2], d);
        Lx[q] = L.x; Ly[q] = L.y;
        xr[q] = 0.f; xi[q] = 0.f;
    }

    if (chunk > 0) {
        float pr[4], pi[4];
        #pragma unroll
        for (int q = 0; q < 4; q++) { pr[q] = Lx[q]; pi[q] = Ly[q]; }
        #pragma unroll
        for (int i = 0; i < 7; i++) {
            #pragma unroll
            for (int q = 0; q < 4; q++) {
                float nr = pr[q] * pr[q] - pi[q] * pi[q];
                float ni = 2.f * pr[q] * pi[q];
                pr[q] = nr; pi[q] = ni;
            }
        }
        for (int jj = 0; jj < chunk; jj++) {
            const float4* Ap =
                reinterpret_cast<const float4*>(&g_part[bh][jj][4 * j]);
            float4 A01 = Ap[0], A23 = Ap[1];
            float Ax[4] = {A01.x, A01.z, A23.x, A23.z};
            float Ay[4] = {A01.y, A01.w, A23.y, A23.w};
            #pragma unroll
            for (int q = 0; q < 4; q++) {
                float nr = fmaf(pr[q], xr[q], fmaf(-pi[q], xi[q], Ax[q]));
                float ni = fmaf(pr[q], xi[q], fmaf( pi[q], xr[q], Ay[q]));
                xr[q] = nr; xi[q] = ni;
            }
        }
    }

    int b = bh >> 7, h1 = bh & 127;
    uint32_t off = ((uint32_t)(t0 * BB + b) * HH + h1) * HH + 4 * j;
    const uint32_t stride = (uint32_t)BB * HH * HH;

    #pragma unroll 4
    for (int t = 0; t < CH_T; t++) {
        float2 c = sbu[w][t];
        #pragma unroll
        for (int q = 0; q < 4; q++) {
            float nr = fmaf(Lx[q], xr[q], fmaf(-Ly[q], xi[q], c.x));
            float ni = fmaf(Lx[q], xi[q], fmaf( Ly[q], xr[q], c.y));
            xr[q] = nr; xi[q] = ni;
        }
        stg_cs_v4(out + off, xr[0], xr[1], xr[2], xr[3]);
        off += stride;
    }
}

// ---------------------------------------------------------------------------
// Generic (checked) chunk kernel — fallback for non-standard output configs.
// ---------------------------------------------------------------------------
__global__ void chunk_kernel(float* __restrict__ out,
                             const float* __restrict__ lre,
                             const float* __restrict__ lim,
                             const float* __restrict__ delta,
                             int cmode, size_t lim_floats) {
    __shared__ float2 sbu[CH_T];
    int bh = blockIdx.x, chunk = blockIdx.y, h2 = threadIdx.x;
    int t0 = chunk * CH_T;
    sbu[h2] = g_bu[(size_t)bh * TT + t0 + h2];
    __syncthreads();
    float d  = delta ? delta[0] : 0.01f;
    float2 L = zoh_L(lre[h2], lim[h2], d);
    float xr = 0.f, xi = 0.f;
    if (chunk > 0) {
        float pr = L.x, pi = L.y;
        #pragma unroll
        for (int i = 0; i < 7; i++) {
            float nr = pr * pr - pi * pi, ni = 2.f * pr * pi;
            pr = nr; pi = ni;
        }
        for (int jj = 0; jj < chunk; jj++) {
            float2 A = g_part[bh][jj][h2];
            float nr = fmaf(pr, xr, fmaf(-pi, xi, A.x));
            float ni = fmaf(pr, xi, fmaf( pi, xr, A.y));
            xr = nr; xi = ni;
        }
    }
    int b = bh >> 7, h1 = bh & 127;
    size_t off = ((size_t)(t0 * BB + b) * HH + h1) * HH + h2;
    const size_t stride = (size_t)BB * HH * HH;
    for (int t = 0; t < CH_T; t++) {
        float2 c = sbu[t];
        float nr = fmaf(L.x, xr, fmaf(-L.y, xi, c.x));
        float ni = fmaf(L.x, xi, fmaf( L.y, xr, c.y));
        xr = nr; xi = ni;
        if (cmode) {
            if (off * 2 + 1 < lim_floats)
                reinterpret_cast<float2*>(out)[off] = make_float2(xr, xi);
        } else {
            if (off < lim_floats) out[off] = xr;
        }
        off += stride;
    }
}

// ---------------------------------------------------------------------------
// Host: robust binding (proven) + output-mode decision table.
// ---------------------------------------------------------------------------
extern "C" void kernel_launch(void* const* d_in, const int* in_sizes, int n_in,
                              void* d_out, int out_size) {
    int div = 0;
    for (int i = 0; i < n_in && !div; i++) {
        if (in_sizes[i] == U_ELEMS)     div = 1;
        if (in_sizes[i] == U_ELEMS * 4) div = 4;
    }
    if (!div) div = 1;

    const float* u = nullptr;
    const float* delta = nullptr;
    const float* lam[2]  = {nullptr, nullptr};
    const float* bmat[2] = {nullptr, nullptr};
    int nl = 0, nb = 0, u_idx = -1;

    for (int i = 0; i < n_in; i++) {
        long long s = (long long)in_sizes[i] / div;
        const float* p = (const float*)d_in[i];
        if (s == U_ELEMS)        { u = p; u_idx = i; }
        else if (s == 1)           delta = p;
        else if (s == LAM_ELEMS) { if (nl < 2) lam[nl++] = p; }
        else if (s == B_ELEMS)   { if (nb < 2) bmat[nb++] = p; }
    }

    if ((!u || nl < 2 || nb < 2) && n_in >= 6) {
        u       = (const float*)d_in[0];
        delta   = (const float*)d_in[1];
        lam[0]  = (const float*)d_in[2];
        lam[1]  = (const float*)d_in[3];
        bmat[0] = (const float*)d_in[4];
        bmat[1] = (const float*)d_in[5];
        u_idx = 0; nl = nb = 2;
    }

    bool re_first = (u_idx == 0);
    const float* lre = re_first ? lam[0]  : lam[1];
    const float* lim = re_first ? lam[1]  : lam[0];
    const float* bre = re_first ? bmat[0] : bmat[1];
    const float* bim = re_first ? bmat[1] : bmat[0];

    const long long full_c = (long long)TT * BB * HH * HH;   // 33,554,432
    int cmode; size_t lim_floats;
    long long os = out_size;
    if (os == full_c)          { cmode = 0; lim_floats = (size_t)full_c; }
    else if (os == 2 * full_c) { cmode = 1; lim_floats = (size_t)(2 * full_c); }
    else if (os == 8 * full_c) { cmode = 1; lim_floats = (size_t)(2 * full_c); }
    else if (os == 4 * full_c) { cmode = 0; lim_floats = (size_t)full_c; }
    else { cmode = 0;
           lim_floats = (size_t)(os < full_c ? (os > 0 ? os : 0) : full_c); }

    cudaFuncSetAttribute(gemm_kernel,
                         cudaFuncAttributeMaxDynamicSharedMemorySize,
                         GEMM_SMEM);

    prep_kernel<<<64, 256>>>(bre, bim, lre, lim, delta);
    gemm_kernel<<<dim3(MM / MT, NN / NT), 256, GEMM_SMEM>>>(u);
    partial_kernel<<<dim3(BB * HH, NCH - 1), 128>>>(lre, lim, delta);

    if (cmode == 0 && lim_floats == (size_t)full_c) {
        chunk_fast_kernel<<<dim3(BB * HH / 4, NCH), 128>>>((float*)d_out,
                                                           lre, lim, delta);
    } else {
        chunk_kernel<<<dim3(BB * HH, NCH), 128>>>((float*)d_out, lre, lim,
                                                  delta, cmode, lim_floats);
    }
}

// round 15
// speedup vs baseline: 1.2471x; 1.2471x over previous
#include <cuda_runtime.h>
#include <cuda_bf16.h>
#include <cstdint>

#define TT   1024
#define BB   2
#define HH   128
#define NIN  1024
#define MM   (BB * TT)          // 2048
#define NN   (2 * HH)           // 256
#define CH_T 64
#define NCH  (TT / CH_T)        // 16
#define LOG_CH 6                // log2(CH_T)

#define U_ELEMS   (BB * TT * NIN)
#define LAM_ELEMS (HH)
#define B_ELEMS   (HH * NIN)

// GEMM tiling: CTA 64m x 64n, physical-k chunks of 128, 4 operand tiles
// resident per chunk; 3 term-passes from smem.
#define MT 64
#define NT 64
#define KT2 128
#define NPC (NIN / KT2)         // 8
#define TILE_B (64 * 256)       // 16384
#define BUF_B  (4 * TILE_B)     // 65536
#define GEMM_SMEM (2 * BUF_B)   // 131072

// device scratch
__device__ __nv_bfloat16 g_uhi[MM * NIN];
__device__ __nv_bfloat16 g_ulo[MM * NIN];
__device__ __nv_bfloat16 g_Bhi[NN * NIN];
__device__ __nv_bfloat16 g_Blo[NN * NIN];
__device__ float2 g_bu[MM * HH];                // bu[(b*HH+h)*TT + t]
__device__ float2 g_part[BB * HH][NCH - 1][HH]; // per-chunk partial states

// ---- PTX helpers ----------------------------------------------------------
__device__ __forceinline__ uint32_t smem_u32(const void* p) {
    uint32_t a;
    asm("{ .reg .u64 t; cvta.to.shared.u64 t, %1; cvt.u32.u64 %0, t; }"
        : "=r"(a) : "l"(p));
    return a;
}
__device__ __forceinline__ uint32_t sw128(uint32_t off) {
    return off ^ ((off >> 3) & 0x70);
}
__device__ __forceinline__ void cp16(uint32_t dst, const void* src) {
    asm volatile("cp.async.cg.shared.global [%0], [%1], 16;"
                 :: "r"(dst), "l"(src));
}
__device__ __forceinline__ void cp_commit() {
    asm volatile("cp.async.commit_group;");
}
template <int N> __device__ __forceinline__ void cp_wait() {
    asm volatile("cp.async.wait_group %0;" :: "n"(N));
}
__device__ __forceinline__ void ldsm4(uint32_t& r0, uint32_t& r1,
                                      uint32_t& r2, uint32_t& r3,
                                      uint32_t addr) {
    asm volatile("ldmatrix.sync.aligned.m8n8.x4.shared.b16 {%0,%1,%2,%3}, [%4];"
                 : "=r"(r0), "=r"(r1), "=r"(r2), "=r"(r3) : "r"(addr));
}
__device__ __forceinline__ void mma_bf16(float& c0, float& c1, float& c2,
                                         float& c3, uint32_t a0, uint32_t a1,
                                         uint32_t a2, uint32_t a3,
                                         uint32_t b0, uint32_t b1) {
    asm volatile(
        "mma.sync.aligned.m16n8k16.row.col.f32.bf16.bf16.f32 "
        "{%0,%1,%2,%3}, {%4,%5,%6,%7}, {%8,%9}, {%0,%1,%2,%3};"
        : "+f"(c0), "+f"(c1), "+f"(c2), "+f"(c3)
        : "r"(a0), "r"(a1), "r"(a2), "r"(a3), "r"(b0), "r"(b1));
}
__device__ __forceinline__ void stg_cs_v4(float* p, float a, float b,
                                          float c, float d) {
    asm volatile("st.global.cs.v4.f32 [%0], {%1,%2,%3,%4};"
                 :: "l"(p), "f"(a), "f"(b), "f"(c), "f"(d) : "memory");
}
__device__ __forceinline__ float2 zoh_L(float ar, float ai, float d) {
    float er = expf(ar * d);
    return make_float2(er * cosf(ai * d), er * sinf(ai * d));
}
__device__ __forceinline__ uint32_t pack_bf16(float a, float b) {
    unsigned short ha = __bfloat16_as_ushort(__float2bfloat16(a));
    unsigned short hb = __bfloat16_as_ushort(__float2bfloat16(b));
    return (uint32_t)ha | ((uint32_t)hb << 16);
}

// ---------------------------------------------------------------------------
// prep (high-MLP, R13-proven): 16 elements/thread, 4 float4 loads in flight.
//   blocks [0,512):   u -> bf16 hi/lo
//   blocks [512,576): Bw -> bf16 hi/lo
// ---------------------------------------------------------------------------
__global__ void prep_kernel(const float* __restrict__ u,
                            const float* __restrict__ bre,
                            const float* __restrict__ bim,
                            const float* __restrict__ lre,
                            const float* __restrict__ lim,
                            const float* __restrict__ delta) {
    int blk = blockIdx.x;
    if (blk < 512) {
        if (!u) return;
        int idx = blk * 256 + threadIdx.x;
        int e0 = idx * 16;
        const float4* up = reinterpret_cast<const float4*>(u + e0);
        float4 v[4];
        #pragma unroll
        for (int i = 0; i < 4; i++) v[i] = up[i];
        const float* f = reinterpret_cast<const float*>(v);
        uint32_t vh[8], vl[8];
        #pragma unroll
        for (int i = 0; i < 8; i++) {
            float a = f[2 * i], b = f[2 * i + 1];
            float ah = __bfloat162float(__float2bfloat16(a));
            float bh = __bfloat162float(__float2bfloat16(b));
            vh[i] = pack_bf16(ah, bh);
            vl[i] = pack_bf16(a - ah, b - bh);
        }
        uint4* dh = reinterpret_cast<uint4*>(g_uhi + e0);
        uint4* dl = reinterpret_cast<uint4*>(g_ulo + e0);
        dh[0] = make_uint4(vh[0], vh[1], vh[2], vh[3]);
        dh[1] = make_uint4(vh[4], vh[5], vh[6], vh[7]);
        dl[0] = make_uint4(vl[0], vl[1], vl[2], vl[3]);
        dl[1] = make_uint4(vl[4], vl[5], vl[6], vl[7]);
    } else {
        if (!bre || !bim || !lre || !lim) return;
        float d = delta ? delta[0] : 0.01f;
        int idx = (blk - 512) * 256 + threadIdx.x;
        int n = idx >> 6, k0 = (idx & 63) * 16;
        int h = n >> 1;
        const float4* brp = reinterpret_cast<const float4*>(bre + (size_t)h * NIN + k0);
        const float4* bip = reinterpret_cast<const float4*>(bim + (size_t)h * NIN + k0);
        float4 vr[4], vi[4];
        #pragma unroll
        for (int i = 0; i < 4; i++) { vr[i] = brp[i]; vi[i] = bip[i]; }
        float ar = lre[h], ai = lim[h];
        float2 L = zoh_L(ar, ai, d);
        float nr = L.x - 1.0f, ni = L.y;
        float inv = 1.0f / (ar * ar + ai * ai);
        float wr = (nr * ar + ni * ai) * inv;
        float wi = (ni * ar - nr * ai) * inv;
        const float* br = reinterpret_cast<const float*>(vr);
        const float* bi = reinterpret_cast<const float*>(vi);
        bool im = (n & 1);
        uint32_t vh[8], vl[8];
        #pragma unroll
        for (int i = 0; i < 8; i++) {
            float a = im ? (wr * bi[2*i]   + wi * br[2*i])
                         : (wr * br[2*i]   - wi * bi[2*i]);
            float b = im ? (wr * bi[2*i+1] + wi * br[2*i+1])
                         : (wr * br[2*i+1] - wi * bi[2*i+1]);
            float ah = __bfloat162float(__float2bfloat16(a));
            float bh = __bfloat162float(__float2bfloat16(b));
            vh[i] = pack_bf16(ah, bh);
            vl[i] = pack_bf16(a - ah, b - bh);
        }
        int e0 = n * NIN + k0;
        uint4* dh = reinterpret_cast<uint4*>(g_Bhi + e0);
        uint4* dl = reinterpret_cast<uint4*>(g_Blo + e0);
        dh[0] = make_uint4(vh[0], vh[1], vh[2], vh[3]);
        dh[1] = make_uint4(vh[4], vh[5], vh[6], vh[7]);
        dl[0] = make_uint4(vl[0], vl[1], vl[2], vl[3]);
        dl[1] = make_uint4(vl[4], vl[5], vl[6], vl[7]);
    }
}

// ---------------------------------------------------------------------------
// GEMM (R13-proven): physical-k chunks, 3 term-passes from smem.
// ---------------------------------------------------------------------------
__global__ void __launch_bounds__(256, 1)
gemm_kernel() {
    extern __shared__ __align__(1024) uint8_t smem[];

    int tid = threadIdx.x, wid = tid >> 5, lane = tid & 31;
    int m0 = blockIdx.x * MT;
    int n0 = blockIdx.y * NT;
    int warp_m = wid & 1;
    int warp_n = wid >> 1;

    uint32_t sbase = smem_u32(smem);
    auto tile_base = [&](int buf, int t) -> uint32_t {
        return sbase + (uint32_t)buf * BUF_B + (uint32_t)t * TILE_B;
    };

    uint32_t offA[2][8], offB[8];
    {
        uint32_t rowA = (uint32_t)(warp_m * 32 + (lane & 15));
        uint32_t kbA  = (uint32_t)((lane >> 4) * 16);
        uint32_t rowB = (uint32_t)(warp_n * 16 + (lane & 7) + ((lane >> 4) << 3));
        uint32_t kbB  = (uint32_t)(((lane >> 3) & 1) * 16);
        #pragma unroll
        for (int s = 0; s < 8; s++) {
            uint32_t sub = (uint32_t)(s >> 2) * 8192;
            #pragma unroll
            for (int mt = 0; mt < 2; mt++)
                offA[mt][s] = sub + sw128((rowA + mt * 16) * 128
                                          + (s & 3) * 32 + kbA);
            offB[s] = sub + sw128(rowB * 128 + (s & 3) * 32 + kbB);
        }
    }

    auto load_tile = [&](uint32_t dstbase, const __nv_bfloat16* g) {
        #pragma unroll
        for (int i = 0; i < 4; i++) {
            int idx = i * 256 + tid;
            int r = idx >> 4, s = idx & 15;
            cp16(dstbase + (uint32_t)((s >> 3) * 8192)
                         + sw128((uint32_t)(r * 128 + (s & 7) * 16)),
                 g + (size_t)r * NIN + s * 8);
        }
    };

    auto load_chunk = [&](int c, int buf) {
        int k0 = c * KT2;
        load_tile(tile_base(buf, 0), g_uhi + (size_t)m0 * NIN + k0);
        load_tile(tile_base(buf, 1), g_ulo + (size_t)m0 * NIN + k0);
        load_tile(tile_base(buf, 2), g_Bhi + (size_t)n0 * NIN + k0);
        load_tile(tile_base(buf, 3), g_Blo + (size_t)n0 * NIN + k0);
        cp_commit();
    };

    float acc[2][2][4];
    #pragma unroll
    for (int i = 0; i < 2; i++)
        #pragma unroll
        for (int j = 0; j < 2; j++)
            #pragma unroll
            for (int q = 0; q < 4; q++) acc[i][j][q] = 0.f;

    load_chunk(0, 0);

    for (int c = 0; c < NPC; c++) {
        int buf = c & 1;
        if (c + 1 < NPC) { load_chunk(c + 1, buf ^ 1); cp_wait<1>(); }
        else             { cp_wait<0>(); }
        __syncthreads();

        #pragma unroll
        for (int term = 0; term < 3; term++) {
            uint32_t Ab = tile_base(buf, term == 2 ? 1 : 0);
            uint32_t Bb = tile_base(buf, term == 1 ? 3 : 2);
            #pragma unroll
            for (int s = 0; s < 8; s++) {
                uint32_t a0[4], a1[4], b[4];
                ldsm4(a0[0], a0[1], a0[2], a0[3], Ab + offA[0][s]);
                ldsm4(a1[0], a1[1], a1[2], a1[3], Ab + offA[1][s]);
                ldsm4(b[0],  b[1],  b[2],  b[3],  Bb + offB[s]);
                mma_bf16(acc[0][0][0], acc[0][0][1], acc[0][0][2], acc[0][0][3],
                         a0[0], a0[1], a0[2], a0[3], b[0], b[1]);
                mma_bf16(acc[0][1][0], acc[0][1][1], acc[0][1][2], acc[0][1][3],
                         a0[0], a0[1], a0[2], a0[3], b[2], b[3]);
                mma_bf16(acc[1][0][0], acc[1][0][1], acc[1][0][2], acc[1][0][3],
                         a1[0], a1[1], a1[2], a1[3], b[0], b[1]);
                mma_bf16(acc[1][1][0], acc[1][1][1], acc[1][1][2], acc[1][1][3],
                         a1[0], a1[1], a1[2], a1[3], b[2], b[3]);
            }
        }
        __syncthreads();
    }

    int hb = (n0 >> 1) + warp_n * 8;
    #pragma unroll
    for (int mt = 0; mt < 2; mt++) {
        #pragma unroll
        for (int nt = 0; nt < 2; nt++) {
            int h = hb + nt * 4 + (lane & 3);
            int m1 = m0 + warp_m * 32 + mt * 16 + (lane >> 2);
            int b1 = m1 >> 10, t1 = m1 & 1023;
            g_bu[((size_t)b1 * HH + h) * TT + t1] =
                make_float2(acc[mt][nt][0], acc[mt][nt][1]);
            int m2 = m1 + 8;
            int b2 = m2 >> 10, t2 = m2 & 1023;
            g_bu[((size_t)b2 * HH + h) * TT + t2] =
                make_float2(acc[mt][nt][2], acc[mt][nt][3]);
        }
    }
}

// ---------------------------------------------------------------------------
// Partial kernel: A_c = local scan of chunk c (CH_T=64) from zero.
// Grid (256, NCH-1 = 15), 128 threads.
// ---------------------------------------------------------------------------
__global__ void partial_kernel(const float* __restrict__ lre,
                               const float* __restrict__ lim,
                               const float* __restrict__ delta) {
    __shared__ float2 sbu[CH_T];
    int bh = blockIdx.x;
    int ch = blockIdx.y;
    int h2 = threadIdx.x;

    if (h2 < CH_T) sbu[h2] = g_bu[(size_t)bh * TT + ch * CH_T + h2];
    __syncthreads();

    float d  = delta ? delta[0] : 0.01f;
    float2 L = zoh_L(lre[h2], lim[h2], d);

    float xr = 0.f, xi = 0.f;
    #pragma unroll 4
    for (int t = 0; t < CH_T; t++) {
        float2 c = sbu[t];
        float nr = fmaf(L.x, xr, fmaf(-L.y, xi, c.x));
        float ni = fmaf(L.x, xi, fmaf( L.y, xr, c.y));
        xr = nr; xi = ni;
    }
    g_part[bh][ch][h2] = make_float2(xr, xi);
}

// ---------------------------------------------------------------------------
// FAST chunk kernel: lane owns 4 h2; warp owns a bh row; CH_T=64 chunks
// double the block count (grid (64, 16)) for more store parallelism.
// ---------------------------------------------------------------------------
__global__ void __launch_bounds__(128)
chunk_fast_kernel(float* __restrict__ out,
                  const float* __restrict__ lre,
                  const float* __restrict__ lim,
                  const float* __restrict__ delta) {
    __shared__ float2 sbu[4][CH_T];

    int tid = threadIdx.x;
    int w = tid >> 5, j = tid & 31;
    int bh    = blockIdx.x * 4 + w;
    int chunk = blockIdx.y;
    int t0    = chunk * CH_T;

    const float2* src = g_bu + (size_t)bh * TT + t0;
    #pragma unroll
    for (int i = 0; i < CH_T / 32; i++) sbu[w][i * 32 + j] = src[i * 32 + j];
    __syncwarp();

    float d = delta ? delta[0] : 0.01f;
    float Lx[4], Ly[4], xr[4], xi[4];
    #pragma unroll
    for (int q = 0; q < 4; q++) {
        int h2 = 4 * j + q;
        float2 L = zoh_L(lre[h2], lim[h2], d);
        Lx[q] = L.x; Ly[q] = L.y;
        xr[q] = 0.f; xi[q] = 0.f;
    }

    if (chunk > 0) {
        float pr[4], pi[4];
        #pragma unroll
        for (int q = 0; q < 4; q++) { pr[q] = Lx[q]; pi[q] = Ly[q]; }
        #pragma unroll
        for (int i = 0; i < LOG_CH; i++) {      // P = L^CH_T
            #pragma unroll
            for (int q = 0; q < 4; q++) {
                float nr = pr[q] * pr[q] - pi[q] * pi[q];
                float ni = 2.f * pr[q] * pi[q];
                pr[q] = nr; pi[q] = ni;
            }
        }
        for (int jj = 0; jj < chunk; jj++) {
            const float4* Ap =
                reinterpret_cast<const float4*>(&g_part[bh][jj][4 * j]);
            float4 A01 = Ap[0], A23 = Ap[1];
            float Ax[4] = {A01.x, A01.z, A23.x, A23.z};
            float Ay[4] = {A01.y, A01.w, A23.y, A23.w};
            #pragma unroll
            for (int q = 0; q < 4; q++) {
                float nr = fmaf(pr[q], xr[q], fmaf(-pi[q], xi[q], Ax[q]));
                float ni = fmaf(pr[q], xi[q], fmaf( pi[q], xr[q], Ay[q]));
                xr[q] = nr; xi[q] = ni;
            }
        }
    }

    int b = bh >> 7, h1 = bh & 127;
    uint32_t off = ((uint32_t)(t0 * BB + b) * HH + h1) * HH + 4 * j;
    const uint32_t stride = (uint32_t)BB * HH * HH;

    #pragma unroll 4
    for (int t = 0; t < CH_T; t++) {
        float2 c = sbu[w][t];
        #pragma unroll
        for (int q = 0; q < 4; q++) {
            float nr = fmaf(Lx[q], xr[q], fmaf(-Ly[q], xi[q], c.x));
            float ni = fmaf(Lx[q], xi[q], fmaf( Ly[q], xr[q], c.y));
            xr[q] = nr; xi[q] = ni;
        }
        stg_cs_v4(out + off, xr[0], xr[1], xr[2], xr[3]);
        off += stride;
    }
}

// ---------------------------------------------------------------------------
// Generic (checked) chunk kernel — fallback for non-standard output configs.
// ---------------------------------------------------------------------------
__global__ void chunk_kernel(float* __restrict__ out,
                             const float* __restrict__ lre,
                             const float* __restrict__ lim,
                             const float* __restrict__ delta,
                             int cmode, size_t lim_floats) {
    __shared__ float2 sbu[CH_T];
    int bh = blockIdx.x, chunk = blockIdx.y, h2 = threadIdx.x;
    int t0 = chunk * CH_T;
    if (h2 < CH_T) sbu[h2] = g_bu[(size_t)bh * TT + t0 + h2];
    __syncthreads();
    float d  = delta ? delta[0] : 0.01f;
    float2 L = zoh_L(lre[h2], lim[h2], d);
    float xr = 0.f, xi = 0.f;
    if (chunk > 0) {
        float pr = L.x, pi = L.y;
        #pragma unroll
        for (int i = 0; i < LOG_CH; i++) {
            float nr = pr * pr - pi * pi, ni = 2.f * pr * pi;
            pr = nr; pi = ni;
        }
        for (int jj = 0; jj < chunk; jj++) {
            float2 A = g_part[bh][jj][h2];
            float nr = fmaf(pr, xr, fmaf(-pi, xi, A.x));
            float ni = fmaf(pr, xi, fmaf( pi, xr, A.y));
            xr = nr; xi = ni;
        }
    }
    int b = bh >> 7, h1 = bh & 127;
    size_t off = ((size_t)(t0 * BB + b) * HH + h1) * HH + h2;
    const size_t stride = (size_t)BB * HH * HH;
    for (int t = 0; t < CH_T; t++) {
        float2 c = sbu[t];
        float nr = fmaf(L.x, xr, fmaf(-L.y, xi, c.x));
        float ni = fmaf(L.x, xi, fmaf( L.y, xr, c.y));
        xr = nr; xi = ni;
        if (cmode) {
            if (off * 2 + 1 < lim_floats)
                reinterpret_cast<float2*>(out)[off] = make_float2(xr, xi);
        } else {
            if (off < lim_floats) out[off] = xr;
        }
        off += stride;
    }
}

// ---------------------------------------------------------------------------
// Host: robust binding (proven) + output-mode decision table.
// ---------------------------------------------------------------------------
extern "C" void kernel_launch(void* const* d_in, const int* in_sizes, int n_in,
                              void* d_out, int out_size) {
    int div = 0;
    for (int i = 0; i < n_in && !div; i++) {
        if (in_sizes[i] == U_ELEMS)     div = 1;
        if (in_sizes[i] == U_ELEMS * 4) div = 4;
    }
    if (!div) div = 1;

    const float* u = nullptr;
    const float* delta = nullptr;
    const float* lam[2]  = {nullptr, nullptr};
    const float* bmat[2] = {nullptr, nullptr};
    int nl = 0, nb = 0, u_idx = -1;

    for (int i = 0; i < n_in; i++) {
        long long s = (long long)in_sizes[i] / div;
        const float* p = (const float*)d_in[i];
        if (s == U_ELEMS)        { u = p; u_idx = i; }
        else if (s == 1)           delta = p;
        else if (s == LAM_ELEMS) { if (nl < 2) lam[nl++] = p; }
        else if (s == B_ELEMS)   { if (nb < 2) bmat[nb++] = p; }
    }

    if ((!u || nl < 2 || nb < 2) && n_in >= 6) {
        u       = (const float*)d_in[0];
        delta   = (const float*)d_in[1];
        lam[0]  = (const float*)d_in[2];
        lam[1]  = (const float*)d_in[3];
        bmat[0] = (const float*)d_in[4];
        bmat[1] = (const float*)d_in[5];
        u_idx = 0; nl = nb = 2;
    }

    bool re_first = (u_idx == 0);
    const float* lre = re_first ? lam[0]  : lam[1];
    const float* lim = re_first ? lam[1]  : lam[0];
    const float* bre = re_first ? bmat[0] : bmat[1];
    const float* bim = re_first ? bmat[1] : bmat[0];

    const long long full_c = (long long)TT * BB * HH * HH;   // 33,554,432
    int cmode; size_t lim_floats;
    long long os = out_size;
    if (os == full_c)          { cmode = 0; lim_floats = (size_t)full_c; }
    else if (os == 2 * full_c) { cmode = 1; lim_floats = (size_t)(2 * full_c); }
    else if (os == 8 * full_c) { cmode = 1; lim_floats = (size_t)(2 * full_c); }
    else if (os == 4 * full_c) { cmode = 0; lim_floats = (size_t)full_c; }
    else { cmode = 0;
           lim_floats = (size_t)(os < full_c ? (os > 0 ? os : 0) : full_c); }

    cudaFuncSetAttribute(gemm_kernel,
                         cudaFuncAttributeMaxDynamicSharedMemorySize,
                         GEMM_SMEM);

    prep_kernel<<<576, 256>>>(u, bre, bim, lre, lim, delta);
    gemm_kernel<<<dim3(MM / MT, NN / NT), 256, GEMM_SMEM>>>();
    partial_kernel<<<dim3(BB * HH, NCH - 1), 128>>>(lre, lim, delta);

    if (cmode == 0 && lim_floats == (size_t)full_c) {
        chunk_fast_kernel<<<dim3(BB * HH / 4, NCH), 128>>>((float*)d_out,
                                                           lre, lim, delta);
    } else {
        chunk_kernel<<<dim3(BB * HH, NCH), 128>>>((float*)d_out, lre, lim,
                                                  delta, cmode, lim_floats);
    }
}

// round 16
// speedup vs baseline: 1.3160x; 1.0553x over previous
#include <cuda_runtime.h>
#include <cuda_fp16.h>
#include <cstdint>

#define TT   1024
#define BB   2
#define HH   128
#define NIN  1024
#define MM   (BB * TT)          // 2048
#define NN   (2 * HH)           // 256
#define CH_T 64
#define NCH  (TT / CH_T)        // 16
#define LOG_CH 6

#define U_ELEMS   (BB * TT * NIN)
#define LAM_ELEMS (HH)
#define B_ELEMS   (HH * NIN)

// GEMM tiling: CTA 64m x 64n, physical-k chunks of 128.
// fp16 2-term split: D = uhi*B + ulo*B  (B single fp16 tile).
#define MT 64
#define NT 64
#define KT2 128
#define NPC (NIN / KT2)         // 8
#define TILE_B (64 * 256)       // 16384 bytes per tile (64 rows x 256B)
#define NTILES 3                // uhi, ulo, B
#define BUF_B  (NTILES * TILE_B)    // 49152
#define GEMM_SMEM (2 * BUF_B)       // 98304

// device scratch
__device__ __half g_uhi[MM * NIN];
__device__ __half g_ulo[MM * NIN];
__device__ __half g_B[NN * NIN];
__device__ float2 g_bu[MM * HH];                // bu[(b*HH+h)*TT + t]
__device__ float2 g_part[BB * HH][NCH - 1][HH]; // per-chunk partial states

// ---- PTX helpers ----------------------------------------------------------
__device__ __forceinline__ uint32_t smem_u32(const void* p) {
    uint32_t a;
    asm("{ .reg .u64 t; cvta.to.shared.u64 t, %1; cvt.u32.u64 %0, t; }"
        : "=r"(a) : "l"(p));
    return a;
}
__device__ __forceinline__ uint32_t sw128(uint32_t off) {
    return off ^ ((off >> 3) & 0x70);
}
__device__ __forceinline__ void cp16(uint32_t dst, const void* src) {
    asm volatile("cp.async.cg.shared.global [%0], [%1], 16;"
                 :: "r"(dst), "l"(src));
}
__device__ __forceinline__ void cp_commit() {
    asm volatile("cp.async.commit_group;");
}
template <int N> __device__ __forceinline__ void cp_wait() {
    asm volatile("cp.async.wait_group %0;" :: "n"(N));
}
__device__ __forceinline__ void ldsm4(uint32_t& r0, uint32_t& r1,
                                      uint32_t& r2, uint32_t& r3,
                                      uint32_t addr) {
    asm volatile("ldmatrix.sync.aligned.m8n8.x4.shared.b16 {%0,%1,%2,%3}, [%4];"
                 : "=r"(r0), "=r"(r1), "=r"(r2), "=r"(r3) : "r"(addr));
}
__device__ __forceinline__ void mma_f16(float& c0, float& c1, float& c2,
                                        float& c3, uint32_t a0, uint32_t a1,
                                        uint32_t a2, uint32_t a3,
                                        uint32_t b0, uint32_t b1) {
    asm volatile(
        "mma.sync.aligned.m16n8k16.row.col.f32.f16.f16.f32 "
        "{%0,%1,%2,%3}, {%4,%5,%6,%7}, {%8,%9}, {%0,%1,%2,%3};"
        : "+f"(c0), "+f"(c1), "+f"(c2), "+f"(c3)
        : "r"(a0), "r"(a1), "r"(a2), "r"(a3), "r"(b0), "r"(b1));
}
__device__ __forceinline__ void stg_cs_v4(float* p, float a, float b,
                                          float c, float d) {
    asm volatile("st.global.cs.v4.f32 [%0], {%1,%2,%3,%4};"
                 :: "l"(p), "f"(a), "f"(b), "f"(c), "f"(d) : "memory");
}
__device__ __forceinline__ float2 zoh_L(float ar, float ai, float d) {
    float er = expf(ar * d);
    return make_float2(er * cosf(ai * d), er * sinf(ai * d));
}
__device__ __forceinline__ uint32_t pack_f16(float a, float b) {
    __half ha = __float2half_rn(a), hb = __float2half_rn(b);
    unsigned short ua = __half_as_ushort(ha), ub = __half_as_ushort(hb);
    return (uint32_t)ua | ((uint32_t)ub << 16);
}

// ---------------------------------------------------------------------------
// prep: blocks [0,512):   u -> fp16 hi/lo (16 floats/thread, 4 LDG.128 MLP).
//       blocks [512,576): Bw = w*(bre+i*bim) -> single fp16 tile [n][k].
// ---------------------------------------------------------------------------
__global__ void prep_kernel(const float* __restrict__ u,
                            const float* __restrict__ bre,
                            const float* __restrict__ bim,
                            const float* __restrict__ lre,
                            const float* __restrict__ lim,
                            const float* __restrict__ delta) {
    int blk = blockIdx.x;
    if (blk < 512) {
        if (!u) return;
        int idx = blk * 256 + threadIdx.x;
        int e0 = idx * 16;
        const float4* up = reinterpret_cast<const float4*>(u + e0);
        float4 v[4];
        #pragma unroll
        for (int i = 0; i < 4; i++) v[i] = up[i];
        const float* f = reinterpret_cast<const float*>(v);
        uint32_t vh[8], vl[8];
        #pragma unroll
        for (int i = 0; i < 8; i++) {
            float a = f[2 * i], b = f[2 * i + 1];
            float ah = __half2float(__float2half_rn(a));
            float bh = __half2float(__float2half_rn(b));
            vh[i] = pack_f16(ah, bh);
            vl[i] = pack_f16(a - ah, b - bh);
        }
        uint4* dh = reinterpret_cast<uint4*>(g_uhi + e0);
        uint4* dl = reinterpret_cast<uint4*>(g_ulo + e0);
        dh[0] = make_uint4(vh[0], vh[1], vh[2], vh[3]);
        dh[1] = make_uint4(vh[4], vh[5], vh[6], vh[7]);
        dl[0] = make_uint4(vl[0], vl[1], vl[2], vl[3]);
        dl[1] = make_uint4(vl[4], vl[5], vl[6], vl[7]);
    } else {
        if (!bre || !bim || !lre || !lim) return;
        float d = delta ? delta[0] : 0.01f;
        int idx = (blk - 512) * 256 + threadIdx.x;   // 0..16383
        int n = idx >> 6, k0 = (idx & 63) * 16;
        int h = n >> 1;
        const float4* brp = reinterpret_cast<const float4*>(bre + (size_t)h * NIN + k0);
        const float4* bip = reinterpret_cast<const float4*>(bim + (size_t)h * NIN + k0);
        float4 vr[4], vi[4];
        #pragma unroll
        for (int i = 0; i < 4; i++) { vr[i] = brp[i]; vi[i] = bip[i]; }
        float ar = lre[h], ai = lim[h];
        float2 L = zoh_L(ar, ai, d);
        float nr = L.x - 1.0f, ni = L.y;
        float inv = 1.0f / (ar * ar + ai * ai);
        float wr = (nr * ar + ni * ai) * inv;
        float wi = (ni * ar - nr * ai) * inv;
        const float* br = reinterpret_cast<const float*>(vr);
        const float* bi = reinterpret_cast<const float*>(vi);
        bool im = (n & 1);
        uint32_t vh[8];
        #pragma unroll
        for (int i = 0; i < 8; i++) {
            float a = im ? (wr * bi[2*i]   + wi * br[2*i])
                         : (wr * br[2*i]   - wi * bi[2*i]);
            float b = im ? (wr * bi[2*i+1] + wi * br[2*i+1])
                         : (wr * br[2*i+1] - wi * bi[2*i+1]);
            vh[i] = pack_f16(a, b);
        }
        int e0 = n * NIN + k0;
        uint4* dh = reinterpret_cast<uint4*>(g_B + e0);
        dh[0] = make_uint4(vh[0], vh[1], vh[2], vh[3]);
        dh[1] = make_uint4(vh[4], vh[5], vh[6], vh[7]);
    }
}

// ---------------------------------------------------------------------------
// GEMM (fp16 2-term): per chunk load 3 tiles (uhi, ulo, B); 2 term passes.
// Double-buffered cp.async, 96 KB dynamic smem. Grid (32, 4), 256 threads.
// ---------------------------------------------------------------------------
__global__ void __launch_bounds__(256, 1)
gemm_kernel() {
    extern __shared__ __align__(1024) uint8_t smem[];

    int tid = threadIdx.x, wid = tid >> 5, lane = tid & 31;
    int m0 = blockIdx.x * MT;
    int n0 = blockIdx.y * NT;
    int warp_m = wid & 1;
    int warp_n = wid >> 1;

    uint32_t sbase = smem_u32(smem);
    auto tile_base = [&](int buf, int t) -> uint32_t {
        return sbase + (uint32_t)buf * BUF_B + (uint32_t)t * TILE_B;
    };

    uint32_t offA[2][8], offB[8];
    {
        uint32_t rowA = (uint32_t)(warp_m * 32 + (lane & 15));
        uint32_t kbA  = (uint32_t)((lane >> 4) * 16);
        uint32_t rowB = (uint32_t)(warp_n * 16 + (lane & 7) + ((lane >> 4) << 3));
        uint32_t kbB  = (uint32_t)(((lane >> 3) & 1) * 16);
        #pragma unroll
        for (int s = 0; s < 8; s++) {
            uint32_t sub = (uint32_t)(s >> 2) * 8192;
            #pragma unroll
            for (int mt = 0; mt < 2; mt++)
                offA[mt][s] = sub + sw128((rowA + mt * 16) * 128
                                          + (s & 3) * 32 + kbA);
            offB[s] = sub + sw128(rowB * 128 + (s & 3) * 32 + kbB);
        }
    }

    auto load_tile = [&](uint32_t dstbase, const __half* g) {
        #pragma unroll
        for (int i = 0; i < 4; i++) {
            int idx = i * 256 + tid;
            int r = idx >> 4, s = idx & 15;
            cp16(dstbase + (uint32_t)((s >> 3) * 8192)
                         + sw128((uint32_t)(r * 128 + (s & 7) * 16)),
                 g + (size_t)r * NIN + s * 8);
        }
    };

    auto load_chunk = [&](int c, int buf) {
        int k0 = c * KT2;
        load_tile(tile_base(buf, 0), g_uhi + (size_t)m0 * NIN + k0);
        load_tile(tile_base(buf, 1), g_ulo + (size_t)m0 * NIN + k0);
        load_tile(tile_base(buf, 2), g_B   + (size_t)n0 * NIN + k0);
        cp_commit();
    };

    float acc[2][2][4];
    #pragma unroll
    for (int i = 0; i < 2; i++)
        #pragma unroll
        for (int j = 0; j < 2; j++)
            #pragma unroll
            for (int q = 0; q < 4; q++) acc[i][j][q] = 0.f;

    load_chunk(0, 0);

    for (int c = 0; c < NPC; c++) {
        int buf = c & 1;
        if (c + 1 < NPC) { load_chunk(c + 1, buf ^ 1); cp_wait<1>(); }
        else             { cp_wait<0>(); }
        __syncthreads();

        #pragma unroll
        for (int term = 0; term < 2; term++) {
            uint32_t Ab = tile_base(buf, term);   // 0 = uhi, 1 = ulo
            uint32_t Bb = tile_base(buf, 2);
            #pragma unroll
            for (int s = 0; s < 8; s++) {
                uint32_t a0[4], a1[4], b[4];
                ldsm4(a0[0], a0[1], a0[2], a0[3], Ab + offA[0][s]);
                ldsm4(a1[0], a1[1], a1[2], a1[3], Ab + offA[1][s]);
                ldsm4(b[0],  b[1],  b[2],  b[3],  Bb + offB[s]);
                mma_f16(acc[0][0][0], acc[0][0][1], acc[0][0][2], acc[0][0][3],
                        a0[0], a0[1], a0[2], a0[3], b[0], b[1]);
                mma_f16(acc[0][1][0], acc[0][1][1], acc[0][1][2], acc[0][1][3],
                        a0[0], a0[1], a0[2], a0[3], b[2], b[3]);
                mma_f16(acc[1][0][0], acc[1][0][1], acc[1][0][2], acc[1][0][3],
                        a1[0], a1[1], a1[2], a1[3], b[0], b[1]);
                mma_f16(acc[1][1][0], acc[1][1][1], acc[1][1][2], acc[1][1][3],
                        a1[0], a1[1], a1[2], a1[3], b[2], b[3]);
            }
        }
        __syncthreads();
    }

    int hb = (n0 >> 1) + warp_n * 8;
    #pragma unroll
    for (int mt = 0; mt < 2; mt++) {
        #pragma unroll
        for (int nt = 0; nt < 2; nt++) {
            int h = hb + nt * 4 + (lane & 3);
            int m1 = m0 + warp_m * 32 + mt * 16 + (lane >> 2);
            int b1 = m1 >> 10, t1 = m1 & 1023;
            g_bu[((size_t)b1 * HH + h) * TT + t1] =
                make_float2(acc[mt][nt][0], acc[mt][nt][1]);
            int m2 = m1 + 8;
            int b2 = m2 >> 10, t2 = m2 & 1023;
            g_bu[((size_t)b2 * HH + h) * TT + t2] =
                make_float2(acc[mt][nt][2], acc[mt][nt][3]);
        }
    }
}

// ---------------------------------------------------------------------------
// Partial kernel: A_c = local scan of chunk c (CH_T=64) from zero.
// Grid (256, 15), 128 threads.
// ---------------------------------------------------------------------------
__global__ void partial_kernel(const float* __restrict__ lre,
                               const float* __restrict__ lim,
                               const float* __restrict__ delta) {
    __shared__ float2 sbu[CH_T];
    int bh = blockIdx.x;
    int ch = blockIdx.y;
    int h2 = threadIdx.x;

    if (h2 < CH_T) sbu[h2] = g_bu[(size_t)bh * TT + ch * CH_T + h2];
    __syncthreads();

    float d  = delta ? delta[0] : 0.01f;
    float2 L = zoh_L(lre[h2], lim[h2], d);

    float xr = 0.f, xi = 0.f;
    #pragma unroll 4
    for (int t = 0; t < CH_T; t++) {
        float2 c = sbu[t];
        float nr = fmaf(L.x, xr, fmaf(-L.y, xi, c.x));
        float ni = fmaf(L.x, xi, fmaf( L.y, xr, c.y));
        xr = nr; xi = ni;
    }
    g_part[bh][ch][h2] = make_float2(xr, xi);
}

// ---------------------------------------------------------------------------
// FAST chunk kernel (R15-measured best): lane owns 4 h2; warp owns a bh row.
// Grid (64, 16), 128 threads. Streaming float4 stores.
// ---------------------------------------------------------------------------
__global__ void __launch_bounds__(128)
chunk_fast_kernel(float* __restrict__ out,
                  const float* __restrict__ lre,
                  const float* __restrict__ lim,
                  const float* __restrict__ delta) {
    __shared__ float2 sbu[4][CH_T];

    int tid = threadIdx.x;
    int w = tid >> 5, j = tid & 31;
    int bh    = blockIdx.x * 4 + w;
    int chunk = blockIdx.y;
    int t0    = chunk * CH_T;

    const float2* src = g_bu + (size_t)bh * TT + t0;
    #pragma unroll
    for (int i = 0; i < CH_T / 32; i++) sbu[w][i * 32 + j] = src[i * 32 + j];
    __syncwarp();

    float d = delta ? delta[0] : 0.01f;
    float Lx[4], Ly[4], xr[4], xi[4];
    #pragma unroll
    for (int q = 0; q < 4; q++) {
        int h2 = 4 * j + q;
        float2 L = zoh_L(lre[h2], lim[h2], d);
        Lx[q] = L.x; Ly[q] = L.y;
        xr[q] = 0.f; xi[q] = 0.f;
    }

    if (chunk > 0) {
        float pr[4], pi[4];
        #pragma unroll
        for (int q = 0; q < 4; q++) { pr[q] = Lx[q]; pi[q] = Ly[q]; }
        #pragma unroll
        for (int i = 0; i < LOG_CH; i++) {      // P = L^CH_T
            #pragma unroll
            for (int q = 0; q < 4; q++) {
                float nr = pr[q] * pr[q] - pi[q] * pi[q];
                float ni = 2.f * pr[q] * pi[q];
                pr[q] = nr; pi[q] = ni;
            }
        }
        for (int jj = 0; jj < chunk; jj++) {
            const float4* Ap =
                reinterpret_cast<const float4*>(&g_part[bh][jj][4 * j]);
            float4 A01 = Ap[0], A23 = Ap[1];
            float Ax[4] = {A01.x, A01.z, A23.x, A23.z};
            float Ay[4] = {A01.y, A01.w, A23.y, A23.w};
            #pragma unroll
            for (int q = 0; q < 4; q++) {
                float nr = fmaf(pr[q], xr[q], fmaf(-pi[q], xi[q], Ax[q]));
                float ni = fmaf(pr[q], xi[q], fmaf( pi[q], xr[q], Ay[q]));
                xr[q] = nr; xi[q] = ni;
            }
        }
    }

    int b = bh >> 7, h1 = bh & 127;
    uint32_t off = ((uint32_t)(t0 * BB + b) * HH + h1) * HH + 4 * j;
    const uint32_t stride = (uint32_t)BB * HH * HH;

    #pragma unroll 4
    for (int t = 0; t < CH_T; t++) {
        float2 c = sbu[w][t];
        #pragma unroll
        for (int q = 0; q < 4; q++) {
            float nr = fmaf(Lx[q], xr[q], fmaf(-Ly[q], xi[q], c.x));
            float ni = fmaf(Lx[q], xi[q], fmaf( Ly[q], xr[q], c.y));
            xr[q] = nr; xi[q] = ni;
        }
        stg_cs_v4(out + off, xr[0], xr[1], xr[2], xr[3]);
        off += stride;
    }
}

// ---------------------------------------------------------------------------
// Generic (checked) chunk kernel — fallback for non-standard output configs.
// ---------------------------------------------------------------------------
__global__ void chunk_kernel(float* __restrict__ out,
                             const float* __restrict__ lre,
                             const float* __restrict__ lim,
                             const float* __restrict__ delta,
                             int cmode, size_t lim_floats) {
    __shared__ float2 sbu[CH_T];
    int bh = blockIdx.x, chunk = blockIdx.y, h2 = threadIdx.x;
    int t0 = chunk * CH_T;
    if (h2 < CH_T) sbu[h2] = g_bu[(size_t)bh * TT + t0 + h2];
    __syncthreads();
    float d  = delta ? delta[0] : 0.01f;
    float2 L = zoh_L(lre[h2], lim[h2], d);
    float xr = 0.f, xi = 0.f;
    if (chunk > 0) {
        float pr = L.x, pi = L.y;
        #pragma unroll
        for (int i = 0; i < LOG_CH; i++) {
            float nr = pr * pr - pi * pi, ni = 2.f * pr * pi;
            pr = nr; pi = ni;
        }
        for (int jj = 0; jj < chunk; jj++) {
            float2 A = g_part[bh][jj][h2];
            float nr = fmaf(pr, xr, fmaf(-pi, xi, A.x));
            float ni = fmaf(pr, xi, fmaf( pi, xr, A.y));
            xr = nr; xi = ni;
        }
    }
    int b = bh >> 7, h1 = bh & 127;
    size_t off = ((size_t)(t0 * BB + b) * HH + h1) * HH + h2;
    const size_t stride = (size_t)BB * HH * HH;
    for (int t = 0; t < CH_T; t++) {
        float2 c = sbu[t];
        float nr = fmaf(L.x, xr, fmaf(-L.y, xi, c.x));
        float ni = fmaf(L.x, xi, fmaf( L.y, xr, c.y));
        xr = nr; xi = ni;
        if (cmode) {
            if (off * 2 + 1 < lim_floats)
                reinterpret_cast<float2*>(out)[off] = make_float2(xr, xi);
        } else {
            if (off < lim_floats) out[off] = xr;
        }
        off += stride;
    }
}

// ---------------------------------------------------------------------------
// Host: robust binding (proven) + output-mode decision table.
// ---------------------------------------------------------------------------
extern "C" void kernel_launch(void* const* d_in, const int* in_sizes, int n_in,
                              void* d_out, int out_size) {
    int div = 0;
    for (int i = 0; i < n_in && !div; i++) {
        if (in_sizes[i] == U_ELEMS)     div = 1;
        if (in_sizes[i] == U_ELEMS * 4) div = 4;
    }
    if (!div) div = 1;

    const float* u = nullptr;
    const float* delta = nullptr;
    const float* lam[2]  = {nullptr, nullptr};
    const float* bmat[2] = {nullptr, nullptr};
    int nl = 0, nb = 0, u_idx = -1;

    for (int i = 0; i < n_in; i++) {
        long long s = (long long)in_sizes[i] / div;
        const float* p = (const float*)d_in[i];
        if (s == U_ELEMS)        { u = p; u_idx = i; }
        else if (s == 1)           delta = p;
        else if (s == LAM_ELEMS) { if (nl < 2) lam[nl++] = p; }
        else if (s == B_ELEMS)   { if (nb < 2) bmat[nb++] = p; }
    }

    if ((!u || nl < 2 || nb < 2) && n_in >= 6) {
        u       = (const float*)d_in[0];
        delta   = (const float*)d_in[1];
        lam[0]  = (const float*)d_in[2];
        lam[1]  = (const float*)d_in[3];
        bmat[0] = (const float*)d_in[4];
        bmat[1] = (const float*)d_in[5];
        u_idx = 0; nl = nb = 2;
    }

    bool re_first = (u_idx == 0);
    const float* lre = re_first ? lam[0]  : lam[1];
    const float* lim = re_first ? lam[1]  : lam[0];
    const float* bre = re_first ? bmat[0] : bmat[1];
    const float* bim = re_first ? bmat[1] : bmat[0];

    const long long full_c = (long long)TT * BB * HH * HH;   // 33,554,432
    int cmode; size_t lim_floats;
    long long os = out_size;
    if (os == full_c)          { cmode = 0; lim_floats = (size_t)full_c; }
    else if (os == 2 * full_c) { cmode = 1; lim_floats = (size_t)(2 * full_c); }
    else if (os == 8 * full_c) { cmode = 1; lim_floats = (size_t)(2 * full_c); }
    else if (os == 4 * full_c) { cmode = 0; lim_floats = (size_t)full_c; }
    else { cmode = 0;
           lim_floats = (size_t)(os < full_c ? (os > 0 ? os : 0) : full_c); }

    cudaFuncSetAttribute(gemm_kernel,
                         cudaFuncAttributeMaxDynamicSharedMemorySize,
                         GEMM_SMEM);

    prep_kernel<<<576, 256>>>(u, bre, bim, lre, lim, delta);
    gemm_kernel<<<dim3(MM / MT, NN / NT), 256, GEMM_SMEM>>>();
    partial_kernel<<<dim3(BB * HH, NCH - 1), 128>>>(lre, lim, delta);

    if (cmode == 0 && lim_floats == (size_t)full_c) {
        chunk_fast_kernel<<<dim3(BB * HH / 4, NCH), 128>>>((float*)d_out,
                                                           lre, lim, delta);
    } else {
        chunk_kernel<<<dim3(BB * HH, NCH), 128>>>((float*)d_out, lre, lim,
                                                  delta, cmode, lim_floats);
    }
}

// round 17
// speedup vs baseline: 1.4284x; 1.0854x over previous
#include <cuda_runtime.h>
#include <cuda_fp16.h>
#include <cstdint>

#define TT   1024
#define BB   2
#define HH   128
#define NIN  1024
#define MM   (BB * TT)          // 2048
#define NN   (2 * HH)           // 256
#define CH_T 64
#define NCH  (TT / CH_T)        // 16
#define LOG_CH 6

#define U_ELEMS   (BB * TT * NIN)
#define LAM_ELEMS (HH)
#define B_ELEMS   (HH * NIN)

// GEMM tiling: CTA 64m x 64n, physical-k chunks of 128.
// Pure fp16 single-term: D = u_f16 * B_f16 (error ~3e-4, calibrated R16).
#define MT 64
#define NT 64
#define KT2 128
#define NPC (NIN / KT2)         // 8
#define TILE_B (64 * 256)       // 16384 bytes per tile (64 rows x 256B)
#define NTILES 2                // u, B
#define BUF_B  (NTILES * TILE_B)    // 32768
#define GEMM_SMEM (2 * BUF_B)       // 65536

// device scratch
__device__ __half g_u16[MM * NIN];
__device__ __half g_B[NN * NIN];
__device__ float2 g_bu[MM * HH];                // bu[(b*HH+h)*TT + t]
__device__ float2 g_part[BB * HH][NCH - 1][HH]; // per-chunk partial states

// ---- PTX helpers ----------------------------------------------------------
__device__ __forceinline__ uint32_t smem_u32(const void* p) {
    uint32_t a;
    asm("{ .reg .u64 t; cvta.to.shared.u64 t, %1; cvt.u32.u64 %0, t; }"
        : "=r"(a) : "l"(p));
    return a;
}
__device__ __forceinline__ uint32_t sw128(uint32_t off) {
    return off ^ ((off >> 3) & 0x70);
}
__device__ __forceinline__ void cp16(uint32_t dst, const void* src) {
    asm volatile("cp.async.cg.shared.global [%0], [%1], 16;"
                 :: "r"(dst), "l"(src));
}
__device__ __forceinline__ void cp_commit() {
    asm volatile("cp.async.commit_group;");
}
template <int N> __device__ __forceinline__ void cp_wait() {
    asm volatile("cp.async.wait_group %0;" :: "n"(N));
}
__device__ __forceinline__ void ldsm4(uint32_t& r0, uint32_t& r1,
                                      uint32_t& r2, uint32_t& r3,
                                      uint32_t addr) {
    asm volatile("ldmatrix.sync.aligned.m8n8.x4.shared.b16 {%0,%1,%2,%3}, [%4];"
                 : "=r"(r0), "=r"(r1), "=r"(r2), "=r"(r3) : "r"(addr));
}
__device__ __forceinline__ void mma_f16(float& c0, float& c1, float& c2,
                                        float& c3, uint32_t a0, uint32_t a1,
                                        uint32_t a2, uint32_t a3,
                                        uint32_t b0, uint32_t b1) {
    asm volatile(
        "mma.sync.aligned.m16n8k16.row.col.f32.f16.f16.f32 "
        "{%0,%1,%2,%3}, {%4,%5,%6,%7}, {%8,%9}, {%0,%1,%2,%3};"
        : "+f"(c0), "+f"(c1), "+f"(c2), "+f"(c3)
        : "r"(a0), "r"(a1), "r"(a2), "r"(a3), "r"(b0), "r"(b1));
}
__device__ __forceinline__ void stg_cs_v4(float* p, float a, float b,
                                          float c, float d) {
    asm volatile("st.global.cs.v4.f32 [%0], {%1,%2,%3,%4};"
                 :: "l"(p), "f"(a), "f"(b), "f"(c), "f"(d) : "memory");
}
__device__ __forceinline__ float2 zoh_L(float ar, float ai, float d) {
    float er = expf(ar * d);
    return make_float2(er * cosf(ai * d), er * sinf(ai * d));
}
__device__ __forceinline__ uint32_t pack_f16(float a, float b) {
    __half ha = __float2half_rn(a), hb = __float2half_rn(b);
    unsigned short ua = __half_as_ushort(ha), ub = __half_as_ushort(hb);
    return (uint32_t)ua | ((uint32_t)ub << 16);
}

// ---------------------------------------------------------------------------
// prep: blocks [0,512):   u -> fp16 (16 floats/thread, 4 LDG.128 in flight).
//       blocks [512,576): Bw = w*(bre+i*bim) -> fp16 tile [n][k].
// ---------------------------------------------------------------------------
__global__ void prep_kernel(const float* __restrict__ u,
                            const float* __restrict__ bre,
                            const float* __restrict__ bim,
                            const float* __restrict__ lre,
                            const float* __restrict__ lim,
                            const float* __restrict__ delta) {
    int blk = blockIdx.x;
    if (blk < 512) {
        if (!u) return;
        int idx = blk * 256 + threadIdx.x;
        int e0 = idx * 16;
        const float4* up = reinterpret_cast<const float4*>(u + e0);
        float4 v[4];
        #pragma unroll
        for (int i = 0; i < 4; i++) v[i] = up[i];
        const float* f = reinterpret_cast<const float*>(v);
        uint32_t vh[8];
        #pragma unroll
        for (int i = 0; i < 8; i++)
            vh[i] = pack_f16(f[2 * i], f[2 * i + 1]);
        uint4* dh = reinterpret_cast<uint4*>(g_u16 + e0);
        dh[0] = make_uint4(vh[0], vh[1], vh[2], vh[3]);
        dh[1] = make_uint4(vh[4], vh[5], vh[6], vh[7]);
    } else {
        if (!bre || !bim || !lre || !lim) return;
        float d = delta ? delta[0] : 0.01f;
        int idx = (blk - 512) * 256 + threadIdx.x;   // 0..16383
        int n = idx >> 6, k0 = (idx & 63) * 16;
        int h = n >> 1;
        const float4* brp = reinterpret_cast<const float4*>(bre + (size_t)h * NIN + k0);
        const float4* bip = reinterpret_cast<const float4*>(bim + (size_t)h * NIN + k0);
        float4 vr[4], vi[4];
        #pragma unroll
        for (int i = 0; i < 4; i++) { vr[i] = brp[i]; vi[i] = bip[i]; }
        float ar = lre[h], ai = lim[h];
        float2 L = zoh_L(ar, ai, d);
        float nr = L.x - 1.0f, ni = L.y;
        float inv = 1.0f / (ar * ar + ai * ai);
        float wr = (nr * ar + ni * ai) * inv;
        float wi = (ni * ar - nr * ai) * inv;
        const float* br = reinterpret_cast<const float*>(vr);
        const float* bi = reinterpret_cast<const float*>(vi);
        bool im = (n & 1);
        uint32_t vh[8];
        #pragma unroll
        for (int i = 0; i < 8; i++) {
            float a = im ? (wr * bi[2*i]   + wi * br[2*i])
                         : (wr * br[2*i]   - wi * bi[2*i]);
            float b = im ? (wr * bi[2*i+1] + wi * br[2*i+1])
                         : (wr * br[2*i+1] - wi * bi[2*i+1]);
            vh[i] = pack_f16(a, b);
        }
        int e0 = n * NIN + k0;
        uint4* dh = reinterpret_cast<uint4*>(g_B + e0);
        dh[0] = make_uint4(vh[0], vh[1], vh[2], vh[3]);
        dh[1] = make_uint4(vh[4], vh[5], vh[6], vh[7]);
    }
}

// ---------------------------------------------------------------------------
// GEMM (pure fp16): per chunk load 2 tiles (u, B), single MMA pass.
// Double-buffered cp.async, 64 KB dynamic smem. Grid (32, 4), 256 threads.
// ---------------------------------------------------------------------------
__global__ void __launch_bounds__(256, 1)
gemm_kernel() {
    extern __shared__ __align__(1024) uint8_t smem[];

    int tid = threadIdx.x, wid = tid >> 5, lane = tid & 31;
    int m0 = blockIdx.x * MT;
    int n0 = blockIdx.y * NT;
    int warp_m = wid & 1;
    int warp_n = wid >> 1;

    uint32_t sbase = smem_u32(smem);
    auto tile_base = [&](int buf, int t) -> uint32_t {
        return sbase + (uint32_t)buf * BUF_B + (uint32_t)t * TILE_B;
    };

    uint32_t offA[2][8], offB[8];
    {
        uint32_t rowA = (uint32_t)(warp_m * 32 + (lane & 15));
        uint32_t kbA  = (uint32_t)((lane >> 4) * 16);
        uint32_t rowB = (uint32_t)(warp_n * 16 + (lane & 7) + ((lane >> 4) << 3));
        uint32_t kbB  = (uint32_t)(((lane >> 3) & 1) * 16);
        #pragma unroll
        for (int s = 0; s < 8; s++) {
            uint32_t sub = (uint32_t)(s >> 2) * 8192;
            #pragma unroll
            for (int mt = 0; mt < 2; mt++)
                offA[mt][s] = sub + sw128((rowA + mt * 16) * 128
                                          + (s & 3) * 32 + kbA);
            offB[s] = sub + sw128(rowB * 128 + (s & 3) * 32 + kbB);
        }
    }

    auto load_tile = [&](uint32_t dstbase, const __half* g) {
        #pragma unroll
        for (int i = 0; i < 4; i++) {
            int idx = i * 256 + tid;
            int r = idx >> 4, s = idx & 15;
            cp16(dstbase + (uint32_t)((s >> 3) * 8192)
                         + sw128((uint32_t)(r * 128 + (s & 7) * 16)),
                 g + (size_t)r * NIN + s * 8);
        }
    };

    auto load_chunk = [&](int c, int buf) {
        int k0 = c * KT2;
        load_tile(tile_base(buf, 0), g_u16 + (size_t)m0 * NIN + k0);
        load_tile(tile_base(buf, 1), g_B   + (size_t)n0 * NIN + k0);
        cp_commit();
    };

    float acc[2][2][4];
    #pragma unroll
    for (int i = 0; i < 2; i++)
        #pragma unroll
        for (int j = 0; j < 2; j++)
            #pragma unroll
            for (int q = 0; q < 4; q++) acc[i][j][q] = 0.f;

    load_chunk(0, 0);

    for (int c = 0; c < NPC; c++) {
        int buf = c & 1;
        if (c + 1 < NPC) { load_chunk(c + 1, buf ^ 1); cp_wait<1>(); }
        else             { cp_wait<0>(); }
        __syncthreads();

        uint32_t Ab = tile_base(buf, 0);
        uint32_t Bb = tile_base(buf, 1);
        #pragma unroll
        for (int s = 0; s < 8; s++) {
            uint32_t a0[4], a1[4], b[4];
            ldsm4(a0[0], a0[1], a0[2], a0[3], Ab + offA[0][s]);
            ldsm4(a1[0], a1[1], a1[2], a1[3], Ab + offA[1][s]);
            ldsm4(b[0],  b[1],  b[2],  b[3],  Bb + offB[s]);
            mma_f16(acc[0][0][0], acc[0][0][1], acc[0][0][2], acc[0][0][3],
                    a0[0], a0[1], a0[2], a0[3], b[0], b[1]);
            mma_f16(acc[0][1][0], acc[0][1][1], acc[0][1][2], acc[0][1][3],
                    a0[0], a0[1], a0[2], a0[3], b[2], b[3]);
            mma_f16(acc[1][0][0], acc[1][0][1], acc[1][0][2], acc[1][0][3],
                    a1[0], a1[1], a1[2], a1[3], b[0], b[1]);
            mma_f16(acc[1][1][0], acc[1][1][1], acc[1][1][2], acc[1][1][3],
                    a1[0], a1[1], a1[2], a1[3], b[2], b[3]);
        }
        __syncthreads();
    }

    int hb = (n0 >> 1) + warp_n * 8;
    #pragma unroll
    for (int mt = 0; mt < 2; mt++) {
        #pragma unroll
        for (int nt = 0; nt < 2; nt++) {
            int h = hb + nt * 4 + (lane & 3);
            int m1 = m0 + warp_m * 32 + mt * 16 + (lane >> 2);
            int b1 = m1 >> 10, t1 = m1 & 1023;
            g_bu[((size_t)b1 * HH + h) * TT + t1] =
                make_float2(acc[mt][nt][0], acc[mt][nt][1]);
            int m2 = m1 + 8;
            int b2 = m2 >> 10, t2 = m2 & 1023;
            g_bu[((size_t)b2 * HH + h) * TT + t2] =
                make_float2(acc[mt][nt][2], acc[mt][nt][3]);
        }
    }
}

// ---------------------------------------------------------------------------
// Partial kernel: A_c = local scan of chunk c (CH_T=64) from zero.
// Grid (256, 15), 128 threads.
// ---------------------------------------------------------------------------
__global__ void partial_kernel(const float* __restrict__ lre,
                               const float* __restrict__ lim,
                               const float* __restrict__ delta) {
    __shared__ float2 sbu[CH_T];
    int bh = blockIdx.x;
    int ch = blockIdx.y;
    int h2 = threadIdx.x;

    if (h2 < CH_T) sbu[h2] = g_bu[(size_t)bh * TT + ch * CH_T + h2];
    __syncthreads();

    float d  = delta ? delta[0] : 0.01f;
    float2 L = zoh_L(lre[h2], lim[h2], d);

    float xr = 0.f, xi = 0.f;
    #pragma unroll 4
    for (int t = 0; t < CH_T; t++) {
        float2 c = sbu[t];
        float nr = fmaf(L.x, xr, fmaf(-L.y, xi, c.x));
        float ni = fmaf(L.x, xi, fmaf( L.y, xr, c.y));
        xr = nr; xi = ni;
    }
    g_part[bh][ch][h2] = make_float2(xr, xi);
}

// ---------------------------------------------------------------------------
// FAST chunk kernel (measured best): lane owns 4 h2; warp owns a bh row.
// Grid (64, 16), 128 threads. Streaming float4 stores.
// ---------------------------------------------------------------------------
__global__ void __launch_bounds__(128)
chunk_fast_kernel(float* __restrict__ out,
                  const float* __restrict__ lre,
                  const float* __restrict__ lim,
                  const float* __restrict__ delta) {
    __shared__ float2 sbu[4][CH_T];

    int tid = threadIdx.x;
    int w = tid >> 5, j = tid & 31;
    int bh    = blockIdx.x * 4 + w;
    int chunk = blockIdx.y;
    int t0    = chunk * CH_T;

    const float2* src = g_bu + (size_t)bh * TT + t0;
    #pragma unroll
    for (int i = 0; i < CH_T / 32; i++) sbu[w][i * 32 + j] = src[i * 32 + j];
    __syncwarp();

    float d = delta ? delta[0] : 0.01f;
    float Lx[4], Ly[4], xr[4], xi[4];
    #pragma unroll
    for (int q = 0; q < 4; q++) {
        int h2 = 4 * j + q;
        float2 L = zoh_L(lre[h2], lim[h2], d);
        Lx[q] = L.x; Ly[q] = L.y;
        xr[q] = 0.f; xi[q] = 0.f;
    }

    if (chunk > 0) {
        float pr[4], pi[4];
        #pragma unroll
        for (int q = 0; q < 4; q++) { pr[q] = Lx[q]; pi[q] = Ly[q]; }
        #pragma unroll
        for (int i = 0; i < LOG_CH; i++) {      // P = L^CH_T
            #pragma unroll
            for (int q = 0; q < 4; q++) {
                float nr = pr[q] * pr[q] - pi[q] * pi[q];
                float ni = 2.f * pr[q] * pi[q];
                pr[q] = nr; pi[q] = ni;
            }
        }
        for (int jj = 0; jj < chunk; jj++) {
            const float4* Ap =
                reinterpret_cast<const float4*>(&g_part[bh][jj][4 * j]);
            float4 A01 = Ap[0], A23 = Ap[1];
            float Ax[4] = {A01.x, A01.z, A23.x, A23.z};
            float Ay[4] = {A01.y, A01.w, A23.y, A23.w};
            #pragma unroll
            for (int q = 0; q < 4; q++) {
                float nr = fmaf(pr[q], xr[q], fmaf(-pi[q], xi[q], Ax[q]));
                float ni = fmaf(pr[q], xi[q], fmaf( pi[q], xr[q], Ay[q]));
                xr[q] = nr; xi[q] = ni;
            }
        }
    }

    int b = bh >> 7, h1 = bh & 127;
    uint32_t off = ((uint32_t)(t0 * BB + b) * HH + h1) * HH + 4 * j;
    const uint32_t stride = (uint32_t)BB * HH * HH;

    #pragma unroll 4
    for (int t = 0; t < CH_T; t++) {
        float2 c = sbu[w][t];
        #pragma unroll
        for (int q = 0; q < 4; q++) {
            float nr = fmaf(Lx[q], xr[q], fmaf(-Ly[q], xi[q], c.x));
            float ni = fmaf(Lx[q], xi[q], fmaf( Ly[q], xr[q], c.y));
            xr[q] = nr; xi[q] = ni;
        }
        stg_cs_v4(out + off, xr[0], xr[1], xr[2], xr[3]);
        off += stride;
    }
}

// ---------------------------------------------------------------------------
// Generic (checked) chunk kernel — fallback for non-standard output configs.
// ---------------------------------------------------------------------------
__global__ void chunk_kernel(float* __restrict__ out,
                             const float* __restrict__ lre,
                             const float* __restrict__ lim,
                             const float* __restrict__ delta,
                             int cmode, size_t lim_floats) {
    __shared__ float2 sbu[CH_T];
    int bh = blockIdx.x, chunk = blockIdx.y, h2 = threadIdx.x;
    int t0 = chunk * CH_T;
    if (h2 < CH_T) sbu[h2] = g_bu[(size_t)bh * TT + t0 + h2];
    __syncthreads();
    float d  = delta ? delta[0] : 0.01f;
    float2 L = zoh_L(lre[h2], lim[h2], d);
    float xr = 0.f, xi = 0.f;
    if (chunk > 0) {
        float pr = L.x, pi = L.y;
        #pragma unroll
        for (int i = 0; i < LOG_CH; i++) {
            float nr = pr * pr - pi * pi, ni = 2.f * pr * pi;
            pr = nr; pi = ni;
        }
        for (int jj = 0; jj < chunk; jj++) {
            float2 A = g_part[bh][jj][h2];
            float nr = fmaf(pr, xr, fmaf(-pi, xi, A.x));
            float ni = fmaf(pr, xi, fmaf( pi, xr, A.y));
            xr = nr; xi = ni;
        }
    }
    int b = bh >> 7, h1 = bh & 127;
    size_t off = ((size_t)(t0 * BB + b) * HH + h1) * HH + h2;
    const size_t stride = (size_t)BB * HH * HH;
    for (int t = 0; t < CH_T; t++) {
        float2 c = sbu[t];
        float nr = fmaf(L.x, xr, fmaf(-L.y, xi, c.x));
        float ni = fmaf(L.x, xi, fmaf( L.y, xr, c.y));
        xr = nr; xi = ni;
        if (cmode) {
            if (off * 2 + 1 < lim_floats)
                reinterpret_cast<float2*>(out)[off] = make_float2(xr, xi);
        } else {
            if (off < lim_floats) out[off] = xr;
        }
        off += stride;
    }
}

// ---------------------------------------------------------------------------
// Host: robust binding (proven) + output-mode decision table.
// ---------------------------------------------------------------------------
extern "C" void kernel_launch(void* const* d_in, const int* in_sizes, int n_in,
                              void* d_out, int out_size) {
    int div = 0;
    for (int i = 0; i < n_in && !div; i++) {
        if (in_sizes[i] == U_ELEMS)     div = 1;
        if (in_sizes[i] == U_ELEMS * 4) div = 4;
    }
    if (!div) div = 1;

    const float* u = nullptr;
    const float* delta = nullptr;
    const float* lam[2]  = {nullptr, nullptr};
    const float* bmat[2] = {nullptr, nullptr};
    int nl = 0, nb = 0, u_idx = -1;

    for (int i = 0; i < n_in; i++) {
        long long s = (long long)in_sizes[i] / div;
        const float* p = (const float*)d_in[i];
        if (s == U_ELEMS)        { u = p; u_idx = i; }
        else if (s == 1)           delta = p;
        else if (s == LAM_ELEMS) { if (nl < 2) lam[nl++] = p; }
        else if (s == B_ELEMS)   { if (nb < 2) bmat[nb++] = p; }
    }

    if ((!u || nl < 2 || nb < 2) && n_in >= 6) {
        u       = (const float*)d_in[0];
        delta   = (const float*)d_in[1];
        lam[0]  = (const float*)d_in[2];
        lam[1]  = (const float*)d_in[3];
        bmat[0] = (const float*)d_in[4];
        bmat[1] = (const float*)d_in[5];
        u_idx = 0; nl = nb = 2;
    }

    bool re_first = (u_idx == 0);
    const float* lre = re_first ? lam[0]  : lam[1];
    const float* lim = re_first ? lam[1]  : lam[0];
    const float* bre = re_first ? bmat[0] : bmat[1];
    const float* bim = re_first ? bmat[1] : bmat[0];

    const long long full_c = (long long)TT * BB * HH * HH;   // 33,554,432
    int cmode; size_t lim_floats;
    long long os = out_size;
    if (os == full_c)          { cmode = 0; lim_floats = (size_t)full_c; }
    else if (os == 2 * full_c) { cmode = 1; lim_floats = (size_t)(2 * full_c); }
    else if (os == 8 * full_c) { cmode = 1; lim_floats = (size_t)(2 * full_c); }
    else if (os == 4 * full_c) { cmode = 0; lim_floats = (size_t)full_c; }
    else { cmode = 0;
           lim_floats = (size_t)(os < full_c ? (os > 0 ? os : 0) : full_c); }

    cudaFuncSetAttribute(gemm_kernel,
                         cudaFuncAttributeMaxDynamicSharedMemorySize,
                         GEMM_SMEM);

    prep_kernel<<<576, 256>>>(u, bre, bim, lre, lim, delta);
    gemm_kernel<<<dim3(MM / MT, NN / NT), 256, GEMM_SMEM>>>();
    partial_kernel<<<dim3(BB * HH, NCH - 1), 128>>>(lre, lim, delta);

    if (cmode == 0 && lim_floats == (size_t)full_c) {
        chunk_fast_kernel<<<dim3(BB * HH / 4, NCH), 128>>>((float*)d_out,
                                                           lre, lim, delta);
    } else {
        chunk_kernel<<<dim3(BB * HH, NCH), 128>>>((float*)d_out, lre, lim,
                                                  delta, cmode, lim_floats);
    }
}